// round 2
// baseline (speedup 1.0000x reference)
#include <cuda_runtime.h>
#include <cstdint>

typedef unsigned long long u64;

#define GROUPS 8
#define CDIM 32
#define ROWS_PER_GROUP 262144
#define TOTAL_ROWS (GROUPS * ROWS_PER_GROUP)
#define EPSV 1e-5f
#define TITER 5

// ---- pass 1 config ----
#define P1_BLOCKS_PER_GROUP 256
#define P1_GRID (GROUPS * P1_BLOCKS_PER_GROUP)   // 2048
#define P1_ROWS 1024                             // rows per block
#define P1_TILE 128                              // rows per staged tile
#define P1_TILES (P1_ROWS / P1_TILE)             // 8

// channel stride in the staging buffer: 128 floats of samples + pad
#define CH_STRIDE_U64 65                         // 65 u64 = 130 floats
#define CH_STRIDE_F   130

// ---- pass 2 config ----
#define P2_ROWS 256
#define P2_GRID (TOTAL_ROWS / P2_ROWS)           // 8192

// ---- scratch (device globals: allocation-free) ----
__device__ __align__(16) float gCovPart[P1_GRID * 1024];  // 8 MB partial C per block
__device__ __align__(16) float gSumPart[P1_GRID * 32];    // partial channel sums
__device__ __align__(16) float gMt[GROUPS * 1024];        // Mt[g][d][c] = B[c][d]/sqrt(norm)
__device__ __align__(16) float gBias[GROUPS * 32];        // bias[g][c] = -sum_d mu[d]*Mt[d][c]

// ---- f32x2 helpers (sm_100+ packed fp32; ptxas never auto-fuses these) ----
__device__ __forceinline__ u64 pack2(float a, float b) {
    u64 r; asm("mov.b64 %0, {%1, %2};" : "=l"(r) : "f"(a), "f"(b)); return r;
}
__device__ __forceinline__ float2 unpack2(u64 v) {
    float2 r; asm("mov.b64 {%0, %1}, %2;" : "=f"(r.x), "=f"(r.y) : "l"(v)); return r;
}
__device__ __forceinline__ u64 ffma2(u64 a, u64 b, u64 c) {
    u64 d; asm("fma.rn.f32x2 %0, %1, %2, %3;" : "=l"(d) : "l"(a), "l"(b), "l"(c)); return d;
}

// ============================================================================
// Kernel 1: per-block partial channel sums + raw second moment C = sum z z^T
// Block: 256 threads, 1024 rows. Tile 128 rows staged TRANSPOSED in shared as
// sh[c][sample] (stride 130 floats) so f32x2 pairs two consecutive SAMPLES.
// Each warp = one full-C team: lane tc computes the 8x4 tile
// rows [8*(tc>>3), +8) x cols [4*(tc&7), +4); warps take disjoint sample-pairs.
// ============================================================================
__global__ __launch_bounds__(256) void k1_stats(const float4* __restrict__ in4) {
    // union: staging buffer (32*130*4 = 16640 B) then reduction buffer (32768 B)
    __shared__ __align__(16) unsigned char smem_raw[32768];
    u64*   sh64 = (u64*)smem_raw;       // [c][pair], stride CH_STRIDE_U64
    float* red  = (float*)smem_raw;     // [8 warps][1024] after compute
    float* shf  = (float*)smem_raw;     // [c][sample], stride CH_STRIDE_F

    const int t   = threadIdx.x;
    const int bid = blockIdx.x;
    const int w   = t >> 5;
    const int tc  = t & 31;
    const int a   = tc >> 3;   // row-tile 0..3  -> channels 8a..8a+7
    const int b   = tc & 7;    // col-tile 0..7  -> channels 4b..4b+3

    u64 acc[8][4];
#pragma unroll
    for (int i = 0; i < 8; i++)
#pragma unroll
        for (int j = 0; j < 4; j++) acc[i][j] = 0ull;

    float msum[4] = {0.f, 0.f, 0.f, 0.f};   // channel sums for channels 4*(t&7)+i

    const long base4 = (long)bid * (P1_ROWS * 8);

    for (int tile = 0; tile < P1_TILES; tile++) {
        __syncthreads();
        // ---- stage 128 rows (1024 float4), coalesced, transposed store ----
#pragma unroll
        for (int r = 0; r < 4; r++) {
            int f = t + 256 * r;                       // float4 id within tile
            float4 v = in4[base4 + (long)tile * (P1_TILE * 8) + f];
            int s = f >> 3;                            // sample 0..127
            int k = f & 7;                             // float4 slot (== t&7)
            msum[0] += v.x; msum[1] += v.y; msum[2] += v.z; msum[3] += v.w;
            float* dst = shf + (4 * k) * CH_STRIDE_F + s;
            dst[0 * CH_STRIDE_F] = v.x; dst[1 * CH_STRIDE_F] = v.y;
            dst[2 * CH_STRIDE_F] = v.z; dst[3 * CH_STRIDE_F] = v.w;
        }
        __syncthreads();
        // ---- compute: warp w handles pairs p = w, w+8, ..., w+56 ----
#pragma unroll
        for (int pp = 0; pp < 8; pp++) {
            int p = w + 8 * pp;
            u64 zi[8], zj[4];
#pragma unroll
            for (int i = 0; i < 8; i++) zi[i] = sh64[(8 * a + i) * CH_STRIDE_U64 + p];
#pragma unroll
            for (int j = 0; j < 4; j++) zj[j] = sh64[(4 * b + j) * CH_STRIDE_U64 + p];
#pragma unroll
            for (int i = 0; i < 8; i++)
#pragma unroll
                for (int j = 0; j < 4; j++)
                    acc[i][j] = ffma2(zi[i], zj[j], acc[i][j]);
        }
    }
    __syncthreads();
    // ---- per-warp partials -> shared ----
#pragma unroll
    for (int i = 0; i < 8; i++)
#pragma unroll
        for (int j = 0; j < 4; j++) {
            float2 v = unpack2(acc[i][j]);
            red[w * 1024 + (8 * a + i) * 32 + (4 * b + j)] = v.x + v.y;
        }
    __syncthreads();
    // ---- block reduce C (deterministic, fixed order) ----
#pragma unroll
    for (int r = 0; r < 4; r++) {
        int e = t + 256 * r;
        float s = 0.f;
#pragma unroll
        for (int ww = 0; ww < 8; ww++) s += red[ww * 1024 + e];
        gCovPart[(long)bid * 1024 + e] = s;
    }
    __syncthreads();
    // ---- block reduce channel sums ----
    red[t * 4 + 0] = msum[0]; red[t * 4 + 1] = msum[1];
    red[t * 4 + 2] = msum[2]; red[t * 4 + 3] = msum[3];
    __syncthreads();
    if (t < 32) {
        int k = t >> 2, i = t & 3;   // channel t = 4k+i held by threads with (tid&7)==k
        float s = 0.f;
#pragma unroll 8
        for (int q = 0; q < 32; q++) s += red[(q * 8 + k) * 4 + i];
        gSumPart[bid * 32 + t] = s;
    }
}

// ============================================================================
// Kernel 2: reduce partials, build S, Frobenius-normalize, 5x Newton-Schulz,
// emit Mt[g][d][c] = B[c][d]*rsqrt(norm) and bias[g][c]. Grid = 8, block 1024.
// ============================================================================
__global__ __launch_bounds__(1024) void k_solve() {
    __shared__ float S[1024], B[1024], T1[1024], T2[1024];
    __shared__ float mu[32];
    __shared__ float redw[32];
    __shared__ float normsh;

    const int t = threadIdx.x;
    const int g = blockIdx.x;
    const int i = t >> 5, j = t & 31;

    // reduce covariance partials (coalesced over t)
    float cv = 0.f;
    const float* cp = gCovPart + (long)g * P1_BLOCKS_PER_GROUP * 1024;
#pragma unroll 8
    for (int bb = 0; bb < P1_BLOCKS_PER_GROUP; bb++) cv += cp[bb * 1024 + t];
    if (t < 32) {
        float s = 0.f;
        const float* sp = gSumPart + g * P1_BLOCKS_PER_GROUP * 32;
#pragma unroll 8
        for (int bb = 0; bb < P1_BLOCKS_PER_GROUP; bb++) s += sp[bb * 32 + t];
        mu[t] = s * (1.0f / (float)ROWS_PER_GROUP);
    }
    __syncthreads();

    float sij = cv - (float)ROWS_PER_GROUP * mu[i] * mu[j] + ((i == j) ? EPSV : 0.f);

    // Frobenius norm of S
    float v = sij * sij;
#pragma unroll
    for (int o = 16; o; o >>= 1) v += __shfl_xor_sync(0xffffffffu, v, o);
    if (j == 0) redw[i] = v;
    __syncthreads();
    if (t < 32) {
        float x = redw[t];
#pragma unroll
        for (int o = 16; o; o >>= 1) x += __shfl_xor_sync(0xffffffffu, x, o);
        if (t == 0) normsh = sqrtf(x);
    }
    __syncthreads();
    const float nrm = normsh;

    S[t] = sij / nrm;
    B[t] = (i == j) ? 1.f : 0.f;
    __syncthreads();

    for (int it = 0; it < TITER; it++) {
        float s1 = 0.f;
#pragma unroll
        for (int k = 0; k < 32; k++) s1 += B[i * 32 + k] * B[k * 32 + j];
        T1[t] = s1; __syncthreads();
        float s2 = 0.f;
#pragma unroll
        for (int k = 0; k < 32; k++) s2 += T1[i * 32 + k] * B[k * 32 + j];
        T2[t] = s2; __syncthreads();
        float s3 = 0.f;
#pragma unroll
        for (int k = 0; k < 32; k++) s3 += T2[i * 32 + k] * S[k * 32 + j];
        float nb = 1.5f * B[t] - 0.5f * s3;
        __syncthreads();
        B[t] = nb;
        __syncthreads();
    }

    // Mt[d][c] = B[c][d] * rsqrt(norm); here (d,c) = (i,j)
    const float inv = rsqrtf(nrm);
    float mt = B[j * 32 + i] * inv;
    gMt[g * 1024 + t] = mt;
    T1[t] = mt;                      // Mt in shared [d][c]
    __syncthreads();
    if (t < 32) {
        float bsum = 0.f;
#pragma unroll
        for (int d = 0; d < 32; d++) bsum += mu[d] * T1[d * 32 + t];
        gBias[g * 32 + t] = -bsum;
    }
}

// ============================================================================
// Kernel 3: out[n] = z[n] @ Mt + bias. 256 threads, 256 rows per block.
// Thread (q = t>>2, m = t&3) handles rows {R0+q+64*rr} and channels [8m, 8m+8).
// A lane quad (4 lanes) shares the same 4 rows; z[d] broadcast via quad shuffle.
// Fully coalesced LDG/STG; Mt broadcast from shared; f32x2 accumulators.
// ============================================================================
__global__ __launch_bounds__(256) void k2_apply(const float4* __restrict__ in4,
                                                float4* __restrict__ out4) {
    __shared__ __align__(16) u64 mt2[512];   // [d][c2] pairs of Mt channels
    __shared__ u64 bias2[16];

    const int t = threadIdx.x;
    const int g = blockIdx.x >> 10;          // 1024 blocks per group

    const u64* mtg = (const u64*)gMt + g * 512;
    mt2[t] = mtg[t];
    mt2[t + 256] = mtg[t + 256];
    if (t < 16) bias2[t] = ((const u64*)gBias)[g * 16 + t];
    __syncthreads();

    const int lane = t & 31;
    const int m = t & 3;
    const int q = t >> 2;                    // 0..63
    const long R0 = (long)blockIdx.x * P2_ROWS;

    float zf[4][8];
#pragma unroll
    for (int rr = 0; rr < 4; rr++) {
        long rowb = (R0 + q + 64 * rr) * 8;
        float4 v0 = in4[rowb + m * 2 + 0];
        float4 v1 = in4[rowb + m * 2 + 1];
        zf[rr][0] = v0.x; zf[rr][1] = v0.y; zf[rr][2] = v0.z; zf[rr][3] = v0.w;
        zf[rr][4] = v1.x; zf[rr][5] = v1.y; zf[rr][6] = v1.z; zf[rr][7] = v1.w;
    }

    u64 acc[4][4];
#pragma unroll
    for (int rr = 0; rr < 4; rr++)
#pragma unroll
        for (int jj = 0; jj < 4; jj++) acc[rr][jj] = bias2[m * 4 + jj];

    const ulonglong2* mtv = (const ulonglong2*)mt2;
#pragma unroll
    for (int d = 0; d < 32; d++) {
        const int src = (lane & ~3) | (d >> 3);
        ulonglong2 ma = mtv[d * 8 + m * 2 + 0];
        ulonglong2 mb = mtv[d * 8 + m * 2 + 1];
#pragma unroll
        for (int rr = 0; rr < 4; rr++) {
            float z = __shfl_sync(0xffffffffu, zf[rr][d & 7], src);
            u64 zz = pack2(z, z);
            acc[rr][0] = ffma2(zz, ma.x, acc[rr][0]);
            acc[rr][1] = ffma2(zz, ma.y, acc[rr][1]);
            acc[rr][2] = ffma2(zz, mb.x, acc[rr][2]);
            acc[rr][3] = ffma2(zz, mb.y, acc[rr][3]);
        }
    }

#pragma unroll
    for (int rr = 0; rr < 4; rr++) {
        float2 p0 = unpack2(acc[rr][0]), p1 = unpack2(acc[rr][1]);
        float2 p2 = unpack2(acc[rr][2]), p3 = unpack2(acc[rr][3]);
        long rowb = (R0 + q + 64 * rr) * 8;
        out4[rowb + m * 2 + 0] = make_float4(p0.x, p0.y, p1.x, p1.y);
        out4[rowb + m * 2 + 1] = make_float4(p2.x, p2.y, p3.x, p3.y);
    }
}

// ============================================================================
extern "C" void kernel_launch(void* const* d_in, const int* in_sizes, int n_in,
                              void* d_out, int out_size) {
    const float4* in4 = (const float4*)d_in[0];
    float4* out4 = (float4*)d_out;

    k1_stats<<<P1_GRID, 256>>>(in4);
    k_solve<<<GROUPS, 1024>>>();
    k2_apply<<<P2_GRID, 256>>>(in4, out4);
}

// round 3
// speedup vs baseline: 1.0866x; 1.0866x over previous
#include <cuda_runtime.h>
#include <cstdint>

typedef unsigned long long u64;

#define GROUPS 8
#define CDIM 32
#define ROWS_PER_GROUP 262144
#define TOTAL_ROWS (GROUPS * ROWS_PER_GROUP)
#define EPSV 1e-5f
#define TITER 5

// ---- pass 1 config ----
#define P1_BLOCKS_PER_GROUP 256
#define P1_GRID (GROUPS * P1_BLOCKS_PER_GROUP)   // 2048
#define P1_ROWS 1024                             // rows per block
#define P1_WROWS 128                             // rows per warp
#define P1_CHUNK 16                              // rows per warp chunk
#define P1_CHUNKS (P1_WROWS / P1_CHUNK)          // 8

// per-warp staging: 32 channels x 16 samples, u64 stride 9 (odd -> 2-way max)
#define ST64 9                                   // u64 per channel
#define STF  18                                  // floats per channel
#define WBUF_U64 (32 * ST64)                     // 288 u64 = 2304 B per warp

// ---- pass 2 config ----
#define P2_ROWS 128
#define P2_GRID (TOTAL_ROWS / P2_ROWS)           // 16384
#define P2_BLK_PER_GRP (ROWS_PER_GROUP / P2_ROWS) // 2048

// ---- scratch (device globals: allocation-free) ----
__device__ __align__(16) float gCovPart[P1_GRID * 1024];
__device__ __align__(16) float gSumPart[P1_GRID * 32];
__device__ __align__(16) float gMt[GROUPS * 1024];   // Mt[g][d][c] = B[c][d]/sqrt(norm)
__device__ __align__(16) float gBias[GROUPS * 32];   // bias[g][c] = -sum_d mu[d]*Mt[d][c]

// ---- f32x2 helpers ----
__device__ __forceinline__ u64 pack2(float a, float b) {
    u64 r; asm("mov.b64 %0, {%1, %2};" : "=l"(r) : "f"(a), "f"(b)); return r;
}
__device__ __forceinline__ float2 unpack2(u64 v) {
    float2 r; asm("mov.b64 {%0, %1}, %2;" : "=f"(r.x), "=f"(r.y) : "l"(v)); return r;
}
__device__ __forceinline__ u64 ffma2(u64 a, u64 b, u64 c) {
    u64 d; asm("fma.rn.f32x2 %0, %1, %2, %3;" : "=l"(d) : "l"(a), "l"(b), "l"(c)); return d;
}

// ============================================================================
// Kernel 1: partial C = sum z z^T + channel sums.
// Per-warp private staging (no block barriers in main loop) with register
// double-buffer prefetch of the next 16-row chunk. Lane tc owns the 8x4 tile
// rows [8*(tc>>3),+8) x cols [4*(tc&7),+4) of C; f32x2 pairs two samples.
// ============================================================================
__global__ __launch_bounds__(256, 2) void k1_stats(const float4* __restrict__ in4) {
    // union: per-warp staging (8*2304 = 18432 B) then reduction buffer (32768 B)
    __shared__ __align__(16) unsigned char smem_raw[32768];
    float* red = (float*)smem_raw;

    const int t   = threadIdx.x;
    const int bid = blockIdx.x;
    const int w   = t >> 5;
    const int l   = t & 31;
    const int a   = l >> 3;     // row-tile 0..3
    const int b   = l & 7;      // col-tile 0..7
    const int k4  = l & 7;      // float4 slot within row (for staging)
    const int s0  = l >> 3;     // base sample offset (for staging)

    u64*   wbuf  = (u64*)(smem_raw + w * (WBUF_U64 * 8));
    float* wbuff = (float*)wbuf;

    u64 acc[8][4];
#pragma unroll
    for (int i = 0; i < 8; i++)
#pragma unroll
        for (int j = 0; j < 4; j++) acc[i][j] = 0ull;

    float msum[4] = {0.f, 0.f, 0.f, 0.f};   // channels 4*k4 + c

    // global float4 base for this warp's 128 rows
    const long wbase4 = (long)bid * (P1_ROWS * 8) + (long)w * (P1_WROWS * 8);

    // prefetch chunk 0: 16 rows = 128 float4; lane loads f = l + 32*kk
    float4 v[4];
#pragma unroll
    for (int kk = 0; kk < 4; kk++) v[kk] = in4[wbase4 + l + 32 * kk];

    for (int c = 0; c < P1_CHUNKS; c++) {
        __syncwarp();   // prior chunk's LDS reads done before overwrite
        // ---- store staged chunk (transposed) + accumulate channel sums ----
#pragma unroll
        for (int kk = 0; kk < 4; kk++) {
            int s = s0 + 4 * kk;
            float* dst = wbuff + (4 * k4) * STF + s;
            msum[0] += v[kk].x; msum[1] += v[kk].y;
            msum[2] += v[kk].z; msum[3] += v[kk].w;
            dst[0 * STF] = v[kk].x; dst[1 * STF] = v[kk].y;
            dst[2 * STF] = v[kk].z; dst[3 * STF] = v[kk].w;
        }
        // ---- prefetch next chunk (v is dead after the stores above) ----
        if (c + 1 < P1_CHUNKS) {
            long nb = wbase4 + (long)(c + 1) * (P1_CHUNK * 8);
#pragma unroll
            for (int kk = 0; kk < 4; kk++) v[kk] = in4[nb + l + 32 * kk];
        }
        __syncwarp();   // stores visible before reads
        // ---- compute: 8 sample-pairs ----
#pragma unroll
        for (int p = 0; p < 8; p++) {
            u64 zi[8], zj[4];
#pragma unroll
            for (int i = 0; i < 8; i++) zi[i] = wbuf[(8 * a + i) * ST64 + p];
#pragma unroll
            for (int j = 0; j < 4; j++) zj[j] = wbuf[(4 * b + j) * ST64 + p];
#pragma unroll
            for (int i = 0; i < 8; i++)
#pragma unroll
                for (int j = 0; j < 4; j++)
                    acc[i][j] = ffma2(zi[i], zj[j], acc[i][j]);
        }
    }
    __syncthreads();
    // ---- per-warp partials -> shared ----
#pragma unroll
    for (int i = 0; i < 8; i++)
#pragma unroll
        for (int j = 0; j < 4; j++) {
            float2 x = unpack2(acc[i][j]);
            red[w * 1024 + (8 * a + i) * 32 + (4 * b + j)] = x.x + x.y;
        }
    __syncthreads();
    // ---- block reduce C (deterministic, fixed order) ----
#pragma unroll
    for (int r = 0; r < 4; r++) {
        int e = t + 256 * r;
        float s = 0.f;
#pragma unroll
        for (int ww = 0; ww < 8; ww++) s += red[ww * 1024 + e];
        gCovPart[(long)bid * 1024 + e] = s;
    }
    __syncthreads();
    // ---- block reduce channel sums ----
    red[t * 4 + 0] = msum[0]; red[t * 4 + 1] = msum[1];
    red[t * 4 + 2] = msum[2]; red[t * 4 + 3] = msum[3];
    __syncthreads();
    if (t < 32) {
        int kk = t >> 2, i = t & 3;   // channel t = 4kk+i held by threads with (tid&7)==kk
        float s = 0.f;
#pragma unroll 8
        for (int q = 0; q < 32; q++) s += red[(q * 8 + kk) * 4 + i];
        gSumPart[bid * 32 + t] = s;
    }
}

// ============================================================================
// Kernel 2: reduce partials, build S, normalize, 5x Newton-Schulz,
// emit Mt and bias. Grid = 8 groups, block 1024.
// ============================================================================
__global__ __launch_bounds__(1024) void k_solve() {
    __shared__ float S[1024], B[1024], T1[1024], T2[1024];
    __shared__ float mu[32];
    __shared__ float redw[32];
    __shared__ float normsh;

    const int t = threadIdx.x;
    const int g = blockIdx.x;
    const int i = t >> 5, j = t & 31;

    float cv = 0.f;
    const float* cp = gCovPart + (long)g * P1_BLOCKS_PER_GROUP * 1024;
#pragma unroll 8
    for (int bb = 0; bb < P1_BLOCKS_PER_GROUP; bb++) cv += cp[bb * 1024 + t];
    if (t < 32) {
        float s = 0.f;
        const float* sp = gSumPart + g * P1_BLOCKS_PER_GROUP * 32;
#pragma unroll 8
        for (int bb = 0; bb < P1_BLOCKS_PER_GROUP; bb++) s += sp[bb * 32 + t];
        mu[t] = s * (1.0f / (float)ROWS_PER_GROUP);
    }
    __syncthreads();

    float sij = cv - (float)ROWS_PER_GROUP * mu[i] * mu[j] + ((i == j) ? EPSV : 0.f);

    float v = sij * sij;
#pragma unroll
    for (int o = 16; o; o >>= 1) v += __shfl_xor_sync(0xffffffffu, v, o);
    if (j == 0) redw[i] = v;
    __syncthreads();
    if (t < 32) {
        float x = redw[t];
#pragma unroll
        for (int o = 16; o; o >>= 1) x += __shfl_xor_sync(0xffffffffu, x, o);
        if (t == 0) normsh = sqrtf(x);
    }
    __syncthreads();
    const float nrm = normsh;

    S[t] = sij / nrm;
    B[t] = (i == j) ? 1.f : 0.f;
    __syncthreads();

    for (int it = 0; it < TITER; it++) {
        float s1 = 0.f;
#pragma unroll
        for (int k = 0; k < 32; k++) s1 += B[i * 32 + k] * B[k * 32 + j];
        T1[t] = s1; __syncthreads();
        float s2 = 0.f;
#pragma unroll
        for (int k = 0; k < 32; k++) s2 += T1[i * 32 + k] * B[k * 32 + j];
        T2[t] = s2; __syncthreads();
        float s3 = 0.f;
#pragma unroll
        for (int k = 0; k < 32; k++) s3 += T2[i * 32 + k] * S[k * 32 + j];
        float nb = 1.5f * B[t] - 0.5f * s3;
        __syncthreads();
        B[t] = nb;
        __syncthreads();
    }

    const float inv = rsqrtf(nrm);
    float mt = B[j * 32 + i] * inv;
    gMt[g * 1024 + t] = mt;
    T1[t] = mt;
    __syncthreads();
    if (t < 32) {
        float bsum = 0.f;
#pragma unroll
        for (int d = 0; d < 32; d++) bsum += mu[d] * T1[d * 32 + t];
        gBias[g * 32 + t] = -bsum;
    }
}

// ============================================================================
// Kernel 3: out[n] = z[n] @ Mt + bias. 256 threads, 128 rows per block
// (2 rows per thread -> ~55 regs -> 4+ resident blocks, short dep chains).
// Quad-cooperative: 4 lanes share 4 rows, z broadcast via quad shuffle.
// ============================================================================
__global__ __launch_bounds__(256) void k2_apply(const float4* __restrict__ in4,
                                                float4* __restrict__ out4) {
    __shared__ __align__(16) u64 mt2[512];   // [d][c2] pairs of Mt channels
    __shared__ u64 bias2[16];

    const int t = threadIdx.x;
    const int g = blockIdx.x >> 11;          // 2048 blocks per group

    const u64* mtg = (const u64*)gMt + g * 512;
    mt2[t] = mtg[t];
    mt2[t + 256] = mtg[t + 256];
    if (t < 16) bias2[t] = ((const u64*)gBias)[g * 16 + t];
    __syncthreads();

    const int lane = t & 31;
    const int m = t & 3;
    const int q = t >> 2;                    // 0..63
    const long R0 = (long)blockIdx.x * P2_ROWS;

    float zf[2][8];
#pragma unroll
    for (int rr = 0; rr < 2; rr++) {
        long rowb = (R0 + q + 64 * rr) * 8;
        float4 v0 = in4[rowb + m * 2 + 0];
        float4 v1 = in4[rowb + m * 2 + 1];
        zf[rr][0] = v0.x; zf[rr][1] = v0.y; zf[rr][2] = v0.z; zf[rr][3] = v0.w;
        zf[rr][4] = v1.x; zf[rr][5] = v1.y; zf[rr][6] = v1.z; zf[rr][7] = v1.w;
    }

    u64 acc[2][4];
#pragma unroll
    for (int rr = 0; rr < 2; rr++)
#pragma unroll
        for (int jj = 0; jj < 4; jj++) acc[rr][jj] = bias2[m * 4 + jj];

    const ulonglong2* mtv = (const ulonglong2*)mt2;
#pragma unroll
    for (int d = 0; d < 32; d++) {
        const int src = (lane & ~3) | (d >> 3);
        ulonglong2 ma = mtv[d * 8 + m * 2 + 0];
        ulonglong2 mb = mtv[d * 8 + m * 2 + 1];
#pragma unroll
        for (int rr = 0; rr < 2; rr++) {
            float z = __shfl_sync(0xffffffffu, zf[rr][d & 7], src);
            u64 zz = pack2(z, z);
            acc[rr][0] = ffma2(zz, ma.x, acc[rr][0]);
            acc[rr][1] = ffma2(zz, ma.y, acc[rr][1]);
            acc[rr][2] = ffma2(zz, mb.x, acc[rr][2]);
            acc[rr][3] = ffma2(zz, mb.y, acc[rr][3]);
        }
    }

#pragma unroll
    for (int rr = 0; rr < 2; rr++) {
        float2 p0 = unpack2(acc[rr][0]), p1 = unpack2(acc[rr][1]);
        float2 p2 = unpack2(acc[rr][2]), p3 = unpack2(acc[rr][3]);
        long rowb = (R0 + q + 64 * rr) * 8;
        out4[rowb + m * 2 + 0] = make_float4(p0.x, p0.y, p1.x, p1.y);
        out4[rowb + m * 2 + 1] = make_float4(p2.x, p2.y, p3.x, p3.y);
    }
}

// ============================================================================
extern "C" void kernel_launch(void* const* d_in, const int* in_sizes, int n_in,
                              void* d_out, int out_size) {
    const float4* in4 = (const float4*)d_in[0];
    float4* out4 = (float4*)d_out;

    k1_stats<<<P1_GRID, 256>>>(in4);
    k_solve<<<GROUPS, 1024>>>();
    k2_apply<<<P2_GRID, 256>>>(in4, out4);
}

// round 4
// speedup vs baseline: 1.3987x; 1.2872x over previous
#include <cuda_runtime.h>
#include <cstdint>

typedef unsigned long long u64;

#define GROUPS 8
#define CDIM 32
#define ROWS_PER_GROUP 262144
#define TOTAL_ROWS (GROUPS * ROWS_PER_GROUP)
#define EPSV 1e-5f
#define TITER 5

// ---- pass 1 config ----
#define P1_BLOCKS_PER_GROUP 256
#define P1_GRID (GROUPS * P1_BLOCKS_PER_GROUP)   // 2048
#define P1_ROWS 1024                             // rows per block
#define P1_WROWS 128                             // rows per warp
#define P1_CHUNK 16                              // rows per warp chunk
#define P1_CHUNKS (P1_WROWS / P1_CHUNK)          // 8

// staging: [pair p=0..7][channel c=0..31] u64, row stride 34 u64 (272B, 16B-aligned)
#define PSTRIDE 34
#define WBUF_U64 (8 * PSTRIDE)                   // 272 u64 = 2176 B per warp

// ---- reduction stage ----
#define RED_SLICES 32                            // blocks per group in k_red
#define RED_FOLD (P1_BLOCKS_PER_GROUP / RED_SLICES) // 8

// ---- pass 2 config ----
#define P2_ROWS 256
#define P2_GRID (TOTAL_ROWS / P2_ROWS)           // 8192

// ---- scratch (device globals: allocation-free) ----
__device__ __align__(16) float gCovPart[P1_GRID * 1024];
__device__ __align__(16) float gSumPart[P1_GRID * 32];
__device__ __align__(16) float gCov2[GROUPS * RED_SLICES * 1024];
__device__ __align__(16) float gSum2[GROUPS * RED_SLICES * 32];
__device__ __align__(16) float gMt[GROUPS * 1024];   // Mt[g][d][c] = B[c][d]/sqrt(norm)
__device__ __align__(16) float gBias[GROUPS * 32];   // bias[g][c]

// ---- f32x2 helpers ----
__device__ __forceinline__ u64 pack2(float a, float b) {
    u64 r; asm("mov.b64 %0, {%1, %2};" : "=l"(r) : "f"(a), "f"(b)); return r;
}
__device__ __forceinline__ float2 unpack2(u64 v) {
    float2 r; asm("mov.b64 {%0, %1}, %2;" : "=f"(r.x), "=f"(r.y) : "l"(v)); return r;
}
__device__ __forceinline__ u64 ffma2(u64 a, u64 b, u64 c) {
    u64 d; asm("fma.rn.f32x2 %0, %1, %2, %3;" : "=l"(d) : "l"(a), "l"(b), "l"(c)); return d;
}

// ============================================================================
// Kernel 1: partial C = sum z z^T + channel sums.
// Per-warp staging in [pair][channel] u64 layout. Lane (p0=l>>3, k=l&7) loads
// rows 2p, 2p+1 (p = p0, p0+4) at float4 slot k, packs row-pairs in registers,
// stores 2 STS.128 per pair. Compute: pair p uniform across warp; lane (a,b)
// reads zi (4 LDS.128) + zj (2 LDS.128) and does 32 FFMA2.
// ============================================================================
__global__ __launch_bounds__(256, 2) void k1_stats(const float4* __restrict__ in4) {
    __shared__ __align__(16) unsigned char smem_raw[32768];
    float* red = (float*)smem_raw;

    const int t   = threadIdx.x;
    const int bid = blockIdx.x;
    const int w   = t >> 5;
    const int l   = t & 31;
    const int a   = l >> 3;     // row-tile 0..3 (channels 8a..8a+7)
    const int b   = l & 7;      // col-tile 0..7 (channels 4b..4b+3)
    const int k   = l & 7;      // float4 slot (channels 4k..4k+3) for staging
    const int p0  = l >> 3;     // base pair (0..3)

    u64* wbuf = (u64*)(smem_raw + w * (WBUF_U64 * 8));

    u64 acc[8][4];
#pragma unroll
    for (int i = 0; i < 8; i++)
#pragma unroll
        for (int j = 0; j < 4; j++) acc[i][j] = 0ull;

    float msum[4] = {0.f, 0.f, 0.f, 0.f};   // channels 4k + j

    const long wbase4 = (long)bid * (P1_ROWS * 8) + (long)w * (P1_WROWS * 8);

    // prefetch chunk 0: lane handles pairs p0 and p0+4
    float4 va0 = in4[wbase4 + (2 * p0) * 8 + k];
    float4 vb0 = in4[wbase4 + (2 * p0 + 1) * 8 + k];
    float4 va1 = in4[wbase4 + (2 * (p0 + 4)) * 8 + k];
    float4 vb1 = in4[wbase4 + (2 * (p0 + 4) + 1) * 8 + k];

    for (int c = 0; c < P1_CHUNKS; c++) {
        __syncwarp();   // prior chunk's LDS reads done before overwrite
        // ---- pack row-pairs in registers, store 2 STS.128 per pair ----
        {
            msum[0] += va0.x + vb0.x + va1.x + vb1.x;
            msum[1] += va0.y + vb0.y + va1.y + vb1.y;
            msum[2] += va0.z + vb0.z + va1.z + vb1.z;
            msum[3] += va0.w + vb0.w + va1.w + vb1.w;
            ulonglong2* dst0 = (ulonglong2*)(wbuf + p0 * PSTRIDE + 4 * k);
            dst0[0] = make_ulonglong2(pack2(va0.x, vb0.x), pack2(va0.y, vb0.y));
            dst0[1] = make_ulonglong2(pack2(va0.z, vb0.z), pack2(va0.w, vb0.w));
            ulonglong2* dst1 = (ulonglong2*)(wbuf + (p0 + 4) * PSTRIDE + 4 * k);
            dst1[0] = make_ulonglong2(pack2(va1.x, vb1.x), pack2(va1.y, vb1.y));
            dst1[1] = make_ulonglong2(pack2(va1.z, vb1.z), pack2(va1.w, vb1.w));
        }
        // ---- prefetch next chunk ----
        if (c + 1 < P1_CHUNKS) {
            long nb = wbase4 + (long)(c + 1) * (P1_CHUNK * 8);
            va0 = in4[nb + (2 * p0) * 8 + k];
            vb0 = in4[nb + (2 * p0 + 1) * 8 + k];
            va1 = in4[nb + (2 * (p0 + 4)) * 8 + k];
            vb1 = in4[nb + (2 * (p0 + 4) + 1) * 8 + k];
        }
        __syncwarp();   // stores visible before reads
        // ---- compute: 8 pairs, p uniform across warp ----
#pragma unroll
        for (int p = 0; p < 8; p++) {
            const ulonglong2* rowp = (const ulonglong2*)(wbuf + p * PSTRIDE);
            u64 zi[8], zj[4];
#pragma unroll
            for (int i = 0; i < 4; i++) {
                ulonglong2 v = rowp[(8 * a) / 2 + i];
                zi[2 * i] = v.x; zi[2 * i + 1] = v.y;
            }
#pragma unroll
            for (int j = 0; j < 2; j++) {
                ulonglong2 v = rowp[(4 * b) / 2 + j];
                zj[2 * j] = v.x; zj[2 * j + 1] = v.y;
            }
#pragma unroll
            for (int i = 0; i < 8; i++)
#pragma unroll
                for (int j = 0; j < 4; j++)
                    acc[i][j] = ffma2(zi[i], zj[j], acc[i][j]);
        }
    }
    __syncthreads();
    // ---- per-warp partials -> shared ----
#pragma unroll
    for (int i = 0; i < 8; i++)
#pragma unroll
        for (int j = 0; j < 4; j++) {
            float2 x = unpack2(acc[i][j]);
            red[w * 1024 + (8 * a + i) * 32 + (4 * b + j)] = x.x + x.y;
        }
    __syncthreads();
    // ---- block reduce C ----
#pragma unroll
    for (int r = 0; r < 4; r++) {
        int e = t + 256 * r;
        float s = 0.f;
#pragma unroll
        for (int ww = 0; ww < 8; ww++) s += red[ww * 1024 + e];
        gCovPart[(long)bid * 1024 + e] = s;
    }
    __syncthreads();
    // ---- block reduce channel sums ----
    red[t * 4 + 0] = msum[0]; red[t * 4 + 1] = msum[1];
    red[t * 4 + 2] = msum[2]; red[t * 4 + 3] = msum[3];
    __syncthreads();
    if (t < 32) {
        int kk = t >> 2, i = t & 3;
        float s = 0.f;
#pragma unroll 8
        for (int q = 0; q < 32; q++) s += red[(q * 8 + kk) * 4 + i];
        gSumPart[bid * 32 + t] = s;
    }
}

// ============================================================================
// Kernel 1b: fold 2048 partials -> 256 (parallel over 256 blocks)
// ============================================================================
__global__ __launch_bounds__(256) void k_red() {
    const int t = threadIdx.x;
    const int bid = blockIdx.x;             // = g*RED_SLICES + s
    const long base = (long)bid * RED_FOLD; // first partial index

#pragma unroll
    for (int r = 0; r < 4; r++) {
        int e = t + 256 * r;
        float s = 0.f;
#pragma unroll
        for (int f = 0; f < RED_FOLD; f++) s += gCovPart[(base + f) * 1024 + e];
        gCov2[(long)bid * 1024 + e] = s;
    }
    if (t < 32) {
        float s = 0.f;
#pragma unroll
        for (int f = 0; f < RED_FOLD; f++) s += gSumPart[(base + f) * 32 + t];
        gSum2[bid * 32 + t] = s;
    }
}

// ============================================================================
// Kernel 2: final reduce, build S, normalize, 5x Newton-Schulz, emit Mt+bias.
// ============================================================================
__global__ __launch_bounds__(1024) void k_solve() {
    __shared__ float S[1024], B[1024], T1[1024], T2[1024];
    __shared__ float mu[32];
    __shared__ float redw[32];
    __shared__ float normsh;

    const int t = threadIdx.x;
    const int g = blockIdx.x;
    const int i = t >> 5, j = t & 31;

    float cv = 0.f;
    const float* cp = gCov2 + (long)g * RED_SLICES * 1024;
#pragma unroll 8
    for (int bb = 0; bb < RED_SLICES; bb++) cv += cp[bb * 1024 + t];
    if (t < 32) {
        float s = 0.f;
        const float* sp = gSum2 + g * RED_SLICES * 32;
#pragma unroll 8
        for (int bb = 0; bb < RED_SLICES; bb++) s += sp[bb * 32 + t];
        mu[t] = s * (1.0f / (float)ROWS_PER_GROUP);
    }
    __syncthreads();

    float sij = cv - (float)ROWS_PER_GROUP * mu[i] * mu[j] + ((i == j) ? EPSV : 0.f);

    float v = sij * sij;
#pragma unroll
    for (int o = 16; o; o >>= 1) v += __shfl_xor_sync(0xffffffffu, v, o);
    if (j == 0) redw[i] = v;
    __syncthreads();
    if (t < 32) {
        float x = redw[t];
#pragma unroll
        for (int o = 16; o; o >>= 1) x += __shfl_xor_sync(0xffffffffu, x, o);
        if (t == 0) normsh = sqrtf(x);
    }
    __syncthreads();
    const float nrm = normsh;

    S[t] = sij / nrm;
    B[t] = (i == j) ? 1.f : 0.f;
    __syncthreads();

    for (int it = 0; it < TITER; it++) {
        float s1 = 0.f;
#pragma unroll
        for (int kk = 0; kk < 32; kk++) s1 += B[i * 32 + kk] * B[kk * 32 + j];
        T1[t] = s1; __syncthreads();
        float s2 = 0.f;
#pragma unroll
        for (int kk = 0; kk < 32; kk++) s2 += T1[i * 32 + kk] * B[kk * 32 + j];
        T2[t] = s2; __syncthreads();
        float s3 = 0.f;
#pragma unroll
        for (int kk = 0; kk < 32; kk++) s3 += T2[i * 32 + kk] * S[kk * 32 + j];
        float nb = 1.5f * B[t] - 0.5f * s3;
        __syncthreads();
        B[t] = nb;
        __syncthreads();
    }

    const float inv = rsqrtf(nrm);
    float mt = B[j * 32 + i] * inv;
    gMt[g * 1024 + t] = mt;
    T1[t] = mt;
    __syncthreads();
    if (t < 32) {
        float bsum = 0.f;
#pragma unroll
        for (int d = 0; d < 32; d++) bsum += mu[d] * T1[d * 32 + t];
        gBias[g * 32 + t] = -bsum;
    }
}

// ============================================================================
// Kernel 3: out[n] = z[n] @ Mt + bias. 256 threads, 256 rows per block,
// 4 rows/thread. Quad-cooperative with distance-1 software-pipelined shuffle:
// zz for step d+1 is fetched while FFMA2s of step d issue.
// ============================================================================
__global__ __launch_bounds__(256) void k2_apply(const float4* __restrict__ in4,
                                                float4* __restrict__ out4) {
    __shared__ __align__(16) u64 mt2[512];   // [d][c2] pairs of Mt channels
    __shared__ u64 bias2[16];

    const int t = threadIdx.x;
    const int g = blockIdx.x >> 10;          // 1024 blocks per group

    const u64* mtg = (const u64*)gMt + g * 512;
    mt2[t] = mtg[t];
    mt2[t + 256] = mtg[t + 256];
    if (t < 16) bias2[t] = ((const u64*)gBias)[g * 16 + t];
    __syncthreads();

    const int lane = t & 31;
    const int m = t & 3;
    const int q = t >> 2;                    // 0..63
    const long R0 = (long)blockIdx.x * P2_ROWS;

    float zf[4][8];
#pragma unroll
    for (int rr = 0; rr < 4; rr++) {
        long rowb = (R0 + q + 64 * rr) * 8;
        float4 v0 = in4[rowb + m * 2 + 0];
        float4 v1 = in4[rowb + m * 2 + 1];
        zf[rr][0] = v0.x; zf[rr][1] = v0.y; zf[rr][2] = v0.z; zf[rr][3] = v0.w;
        zf[rr][4] = v1.x; zf[rr][5] = v1.y; zf[rr][6] = v1.z; zf[rr][7] = v1.w;
    }

    u64 acc[4][4];
#pragma unroll
    for (int rr = 0; rr < 4; rr++)
#pragma unroll
        for (int jj = 0; jj < 4; jj++) acc[rr][jj] = bias2[m * 4 + jj];

    const ulonglong2* mtv = (const ulonglong2*)mt2;

    // software pipeline: zz for step d prepared at step d-1
    u64 zz[4];
    {
        const int src0 = (lane & ~3);        // d=0 -> owner quad-member 0
#pragma unroll
        for (int rr = 0; rr < 4; rr++) {
            float z = __shfl_sync(0xffffffffu, zf[rr][0], src0);
            zz[rr] = pack2(z, z);
        }
    }
#pragma unroll
    for (int d = 0; d < 32; d++) {
        u64 zc[4];
#pragma unroll
        for (int rr = 0; rr < 4; rr++) zc[rr] = zz[rr];
        if (d + 1 < 32) {
            const int dn = d + 1;
            const int src = (lane & ~3) | (dn >> 3);
#pragma unroll
            for (int rr = 0; rr < 4; rr++) {
                float z = __shfl_sync(0xffffffffu, zf[rr][dn & 7], src);
                zz[rr] = pack2(z, z);
            }
        }
        ulonglong2 ma = mtv[d * 8 + m * 2 + 0];
        ulonglong2 mb = mtv[d * 8 + m * 2 + 1];
#pragma unroll
        for (int rr = 0; rr < 4; rr++) {
            acc[rr][0] = ffma2(zc[rr], ma.x, acc[rr][0]);
            acc[rr][1] = ffma2(zc[rr], ma.y, acc[rr][1]);
            acc[rr][2] = ffma2(zc[rr], mb.x, acc[rr][2]);
            acc[rr][3] = ffma2(zc[rr], mb.y, acc[rr][3]);
        }
    }

#pragma unroll
    for (int rr = 0; rr < 4; rr++) {
        float2 p0 = unpack2(acc[rr][0]), p1 = unpack2(acc[rr][1]);
        float2 p2 = unpack2(acc[rr][2]), p3 = unpack2(acc[rr][3]);
        long rowb = (R0 + q + 64 * rr) * 8;
        out4[rowb + m * 2 + 0] = make_float4(p0.x, p0.y, p1.x, p1.y);
        out4[rowb + m * 2 + 1] = make_float4(p2.x, p2.y, p3.x, p3.y);
    }
}

// ============================================================================
extern "C" void kernel_launch(void* const* d_in, const int* in_sizes, int n_in,
                              void* d_out, int out_size) {
    const float4* in4 = (const float4*)d_in[0];
    float4* out4 = (float4*)d_out;

    k1_stats<<<P1_GRID, 256>>>(in4);
    k_red<<<GROUPS * RED_SLICES, 256>>>();
    k_solve<<<GROUPS, 1024>>>();
    k2_apply<<<P2_GRID, 256>>>(in4, out4);
}

// round 5
// speedup vs baseline: 1.4948x; 1.0687x over previous
#include <cuda_runtime.h>
#include <cstdint>

typedef unsigned long long u64;

#define GROUPS 8
#define CDIM 32
#define ROWS_PER_GROUP 262144
#define TOTAL_ROWS (GROUPS * ROWS_PER_GROUP)
#define EPSV 1e-5f
#define TITER 5

// ---- pass 1 config ----
#define P1_BLOCKS_PER_GROUP 256
#define P1_GRID (GROUPS * P1_BLOCKS_PER_GROUP)   // 2048
#define P1_ROWS 1024                             // rows per block
#define P1_WROWS 128                             // rows per warp
#define P1_CHUNK 16                              // rows per warp chunk
#define P1_CHUNKS (P1_WROWS / P1_CHUNK)          // 8

// staging: [pair p=0..7][channel c=0..31] u64, row stride 34 u64
#define PSTRIDE 34
#define WBUF_U64 (8 * PSTRIDE)                   // 272 u64 = 2176 B per warp

// ---- reduction stage ----
#define RED_SLICES 32
#define RED_FOLD (P1_BLOCKS_PER_GROUP / RED_SLICES) // 8

// ---- pass 2 config ----
#define P2_ROWS 256
#define P2_GRID (TOTAL_ROWS / P2_ROWS)           // 8192
#define ZSTRIDE 34                               // floats per staged row (pad)

// ---- scratch ----
__device__ __align__(16) float gCovPart[P1_GRID * 1024];
__device__ __align__(16) float gSumPart[P1_GRID * 32];
__device__ __align__(16) float gCov2[GROUPS * RED_SLICES * 1024];
__device__ __align__(16) float gSum2[GROUPS * RED_SLICES * 32];
__device__ __align__(16) float gMt[GROUPS * 1024];
__device__ __align__(16) float gBias[GROUPS * 32];

// ---- f32x2 helpers ----
__device__ __forceinline__ u64 pack2(float a, float b) {
    u64 r; asm("mov.b64 %0, {%1, %2};" : "=l"(r) : "f"(a), "f"(b)); return r;
}
__device__ __forceinline__ float2 unpack2(u64 v) {
    float2 r; asm("mov.b64 {%0, %1}, %2;" : "=f"(r.x), "=f"(r.y) : "l"(v)); return r;
}
__device__ __forceinline__ u64 ffma2(u64 a, u64 b, u64 c) {
    u64 d; asm("fma.rn.f32x2 %0, %1, %2, %3;" : "=l"(d) : "l"(a), "l"(b), "l"(c)); return d;
}

// ============================================================================
// Kernel 1: partial C = sum z z^T + channel sums (unchanged from R4).
// ============================================================================
__global__ __launch_bounds__(256, 2) void k1_stats(const float4* __restrict__ in4) {
    __shared__ __align__(16) unsigned char smem_raw[32768];
    float* red = (float*)smem_raw;

    const int t   = threadIdx.x;
    const int bid = blockIdx.x;
    const int w   = t >> 5;
    const int l   = t & 31;
    const int a   = l >> 3;
    const int b   = l & 7;
    const int k   = l & 7;
    const int p0  = l >> 3;

    u64* wbuf = (u64*)(smem_raw + w * (WBUF_U64 * 8));

    u64 acc[8][4];
#pragma unroll
    for (int i = 0; i < 8; i++)
#pragma unroll
        for (int j = 0; j < 4; j++) acc[i][j] = 0ull;

    float msum[4] = {0.f, 0.f, 0.f, 0.f};

    const long wbase4 = (long)bid * (P1_ROWS * 8) + (long)w * (P1_WROWS * 8);

    float4 va0 = in4[wbase4 + (2 * p0) * 8 + k];
    float4 vb0 = in4[wbase4 + (2 * p0 + 1) * 8 + k];
    float4 va1 = in4[wbase4 + (2 * (p0 + 4)) * 8 + k];
    float4 vb1 = in4[wbase4 + (2 * (p0 + 4) + 1) * 8 + k];

    for (int c = 0; c < P1_CHUNKS; c++) {
        __syncwarp();
        {
            msum[0] += va0.x + vb0.x + va1.x + vb1.x;
            msum[1] += va0.y + vb0.y + va1.y + vb1.y;
            msum[2] += va0.z + vb0.z + va1.z + vb1.z;
            msum[3] += va0.w + vb0.w + va1.w + vb1.w;
            ulonglong2* dst0 = (ulonglong2*)(wbuf + p0 * PSTRIDE + 4 * k);
            dst0[0] = make_ulonglong2(pack2(va0.x, vb0.x), pack2(va0.y, vb0.y));
            dst0[1] = make_ulonglong2(pack2(va0.z, vb0.z), pack2(va0.w, vb0.w));
            ulonglong2* dst1 = (ulonglong2*)(wbuf + (p0 + 4) * PSTRIDE + 4 * k);
            dst1[0] = make_ulonglong2(pack2(va1.x, vb1.x), pack2(va1.y, vb1.y));
            dst1[1] = make_ulonglong2(pack2(va1.z, vb1.z), pack2(va1.w, vb1.w));
        }
        if (c + 1 < P1_CHUNKS) {
            long nb = wbase4 + (long)(c + 1) * (P1_CHUNK * 8);
            va0 = in4[nb + (2 * p0) * 8 + k];
            vb0 = in4[nb + (2 * p0 + 1) * 8 + k];
            va1 = in4[nb + (2 * (p0 + 4)) * 8 + k];
            vb1 = in4[nb + (2 * (p0 + 4) + 1) * 8 + k];
        }
        __syncwarp();
#pragma unroll
        for (int p = 0; p < 8; p++) {
            const ulonglong2* rowp = (const ulonglong2*)(wbuf + p * PSTRIDE);
            u64 zi[8], zj[4];
#pragma unroll
            for (int i = 0; i < 4; i++) {
                ulonglong2 v = rowp[(8 * a) / 2 + i];
                zi[2 * i] = v.x; zi[2 * i + 1] = v.y;
            }
#pragma unroll
            for (int j = 0; j < 2; j++) {
                ulonglong2 v = rowp[(4 * b) / 2 + j];
                zj[2 * j] = v.x; zj[2 * j + 1] = v.y;
            }
#pragma unroll
            for (int i = 0; i < 8; i++)
#pragma unroll
                for (int j = 0; j < 4; j++)
                    acc[i][j] = ffma2(zi[i], zj[j], acc[i][j]);
        }
    }
    __syncthreads();
#pragma unroll
    for (int i = 0; i < 8; i++)
#pragma unroll
        for (int j = 0; j < 4; j++) {
            float2 x = unpack2(acc[i][j]);
            red[w * 1024 + (8 * a + i) * 32 + (4 * b + j)] = x.x + x.y;
        }
    __syncthreads();
#pragma unroll
    for (int r = 0; r < 4; r++) {
        int e = t + 256 * r;
        float s = 0.f;
#pragma unroll
        for (int ww = 0; ww < 8; ww++) s += red[ww * 1024 + e];
        gCovPart[(long)bid * 1024 + e] = s;
    }
    __syncthreads();
    red[t * 4 + 0] = msum[0]; red[t * 4 + 1] = msum[1];
    red[t * 4 + 2] = msum[2]; red[t * 4 + 3] = msum[3];
    __syncthreads();
    if (t < 32) {
        int kk = t >> 2, i = t & 3;
        float s = 0.f;
#pragma unroll 8
        for (int q = 0; q < 32; q++) s += red[(q * 8 + kk) * 4 + i];
        gSumPart[bid * 32 + t] = s;
    }
}

// ============================================================================
// Kernel 1b: fold 2048 partials -> 256
// ============================================================================
__global__ __launch_bounds__(256) void k_red() {
    const int t = threadIdx.x;
    const int bid = blockIdx.x;
    const long base = (long)bid * RED_FOLD;

#pragma unroll
    for (int r = 0; r < 4; r++) {
        int e = t + 256 * r;
        float s = 0.f;
#pragma unroll
        for (int f = 0; f < RED_FOLD; f++) s += gCovPart[(base + f) * 1024 + e];
        gCov2[(long)bid * 1024 + e] = s;
    }
    if (t < 32) {
        float s = 0.f;
#pragma unroll
        for (int f = 0; f < RED_FOLD; f++) s += gSumPart[(base + f) * 32 + t];
        gSum2[bid * 32 + t] = s;
    }
}

// ============================================================================
// Kernel 2: final reduce, build S, normalize, Newton-Schulz, emit Mt+bias.
// ============================================================================
__global__ __launch_bounds__(1024) void k_solve() {
    __shared__ float S[1024], B[1024], T1[1024], T2[1024];
    __shared__ float mu[32];
    __shared__ float redw[32];
    __shared__ float normsh;

    const int t = threadIdx.x;
    const int g = blockIdx.x;
    const int i = t >> 5, j = t & 31;

    float cv = 0.f;
    const float* cp = gCov2 + (long)g * RED_SLICES * 1024;
#pragma unroll 8
    for (int bb = 0; bb < RED_SLICES; bb++) cv += cp[bb * 1024 + t];
    if (t < 32) {
        float s = 0.f;
        const float* sp = gSum2 + g * RED_SLICES * 32;
#pragma unroll 8
        for (int bb = 0; bb < RED_SLICES; bb++) s += sp[bb * 32 + t];
        mu[t] = s * (1.0f / (float)ROWS_PER_GROUP);
    }
    __syncthreads();

    float sij = cv - (float)ROWS_PER_GROUP * mu[i] * mu[j] + ((i == j) ? EPSV : 0.f);

    float v = sij * sij;
#pragma unroll
    for (int o = 16; o; o >>= 1) v += __shfl_xor_sync(0xffffffffu, v, o);
    if (j == 0) redw[i] = v;
    __syncthreads();
    if (t < 32) {
        float x = redw[t];
#pragma unroll
        for (int o = 16; o; o >>= 1) x += __shfl_xor_sync(0xffffffffu, x, o);
        if (t == 0) normsh = sqrtf(x);
    }
    __syncthreads();
    const float nrm = normsh;

    S[t] = sij / nrm;
    B[t] = (i == j) ? 1.f : 0.f;
    __syncthreads();

    for (int it = 0; it < TITER; it++) {
        float s1 = 0.f;
#pragma unroll
        for (int kk = 0; kk < 32; kk++) s1 += B[i * 32 + kk] * B[kk * 32 + j];
        T1[t] = s1; __syncthreads();
        float s2 = 0.f;
#pragma unroll
        for (int kk = 0; kk < 32; kk++) s2 += T1[i * 32 + kk] * B[kk * 32 + j];
        T2[t] = s2; __syncthreads();
        float s3 = 0.f;
#pragma unroll
        for (int kk = 0; kk < 32; kk++) s3 += T2[i * 32 + kk] * S[kk * 32 + j];
        float nb = 1.5f * B[t] - 0.5f * s3;
        __syncthreads();
        B[t] = nb;
        __syncthreads();
    }

    const float inv = rsqrtf(nrm);
    float mt = B[j * 32 + i] * inv;
    gMt[g * 1024 + t] = mt;
    T1[t] = mt;
    __syncthreads();
    if (t < 32) {
        float bsum = 0.f;
#pragma unroll
        for (int d = 0; d < 32; d++) bsum += mu[d] * T1[d * 32 + t];
        gBias[g * 32 + t] = -bsum;
    }
}

// ============================================================================
// Kernel 3: out[n] = z[n] @ Mt + bias. NO SHUFFLES.
// z tile (256 rows x 32) staged in shared (stride 34 floats: conflict-free
// LDS.64 reads of d-pairs, 2-way-max STS.64 staging). Thread (q=t>>2, m=t&3)
// owns rows q+64*rr and channels [8m, 8m+8). Per d-pair: 4 LDS.128 (Mt,
// quad-broadcast) + 4 LDS.64 (z) + register splats feed 32 FFMA2.
// ============================================================================
__global__ __launch_bounds__(256, 3) void k2_apply(const float4* __restrict__ in4,
                                                   float4* __restrict__ out4) {
    __shared__ __align__(16) float zbuf[P2_ROWS * ZSTRIDE];  // 34816 B
    __shared__ __align__(16) u64 mt2[512];
    __shared__ u64 bias2[16];

    const int t = threadIdx.x;
    const int g = blockIdx.x >> 10;          // 1024 blocks per group

    const u64* mtg = (const u64*)gMt + g * 512;
    mt2[t] = mtg[t];
    mt2[t + 256] = mtg[t + 256];
    if (t < 16) bias2[t] = ((const u64*)gBias)[g * 16 + t];

    const int m = t & 3;
    const int q = t >> 2;                    // 0..63
    const long R0 = (long)blockIdx.x * P2_ROWS;

    // ---- stage z tile: coalesced LDG.128, STS.64 into padded [row][ch] ----
#pragma unroll
    for (int rr = 0; rr < 4; rr++) {
        int row = q + 64 * rr;
        long rowb = (R0 + row) * 8;
        float4 v0 = in4[rowb + m * 2 + 0];
        float4 v1 = in4[rowb + m * 2 + 1];
        float2* zr = (float2*)(zbuf + row * ZSTRIDE + 8 * m);
        zr[0] = make_float2(v0.x, v0.y);
        zr[1] = make_float2(v0.z, v0.w);
        zr[2] = make_float2(v1.x, v1.y);
        zr[3] = make_float2(v1.z, v1.w);
    }
    __syncthreads();

    u64 acc[4][4];
#pragma unroll
    for (int rr = 0; rr < 4; rr++)
#pragma unroll
        for (int jj = 0; jj < 4; jj++) acc[rr][jj] = bias2[m * 4 + jj];

    const ulonglong2* mtv = (const ulonglong2*)mt2;
#pragma unroll 4
    for (int dp = 0; dp < 16; dp++) {
        const int d0 = 2 * dp;
        ulonglong2 ma0 = mtv[d0 * 8 + m * 2 + 0];
        ulonglong2 mb0 = mtv[d0 * 8 + m * 2 + 1];
        ulonglong2 ma1 = mtv[d0 * 8 + m * 2 + 8];   // (d0+1) row
        ulonglong2 mb1 = mtv[d0 * 8 + m * 2 + 9];
#pragma unroll
        for (int rr = 0; rr < 4; rr++) {
            float2 z2 = *(const float2*)(zbuf + (q + 64 * rr) * ZSTRIDE + d0);
            u64 zz0 = pack2(z2.x, z2.x);
            u64 zz1 = pack2(z2.y, z2.y);
            acc[rr][0] = ffma2(zz0, ma0.x, acc[rr][0]);
            acc[rr][1] = ffma2(zz0, ma0.y, acc[rr][1]);
            acc[rr][2] = ffma2(zz0, mb0.x, acc[rr][2]);
            acc[rr][3] = ffma2(zz0, mb0.y, acc[rr][3]);
            acc[rr][0] = ffma2(zz1, ma1.x, acc[rr][0]);
            acc[rr][1] = ffma2(zz1, ma1.y, acc[rr][1]);
            acc[rr][2] = ffma2(zz1, mb1.x, acc[rr][2]);
            acc[rr][3] = ffma2(zz1, mb1.y, acc[rr][3]);
        }
    }

#pragma unroll
    for (int rr = 0; rr < 4; rr++) {
        float2 p0 = unpack2(acc[rr][0]), p1 = unpack2(acc[rr][1]);
        float2 p2 = unpack2(acc[rr][2]), p3 = unpack2(acc[rr][3]);
        long rowb = (R0 + q + 64 * rr) * 8;
        out4[rowb + m * 2 + 0] = make_float4(p0.x, p0.y, p1.x, p1.y);
        out4[rowb + m * 2 + 1] = make_float4(p2.x, p2.y, p3.x, p3.y);
    }
}

// ============================================================================
extern "C" void kernel_launch(void* const* d_in, const int* in_sizes, int n_in,
                              void* d_out, int out_size) {
    const float4* in4 = (const float4*)d_in[0];
    float4* out4 = (float4*)d_out;

    k1_stats<<<P1_GRID, 256>>>(in4);
    k_red<<<GROUPS * RED_SLICES, 256>>>();
    k_solve<<<GROUPS, 1024>>>();
    k2_apply<<<P2_GRID, 256>>>(in4, out4);
}